// round 2
// baseline (speedup 1.0000x reference)
#include <cuda_runtime.h>
#include <math.h>

#define NN   4096
#define DD   512
#define F1C  64
#define HC   4
#define HF   256   // HC*F1C
#define F2C  32
#define F3C  16
#define MAXD 128

// ---------------- scratch (device globals; no allocation allowed) ----------
__device__ int   g_deg[NN];
__device__ int   g_cols[NN * MAXD];
__device__ float g_Wcat[DD * HF];      // repacked W_heads -> [512][256]
__device__ float g_WhAll[NN * HF];     // Wh for 4 heads, [i][h*64+f]
__device__ float g_s1h[HC * NN];
__device__ float g_s2h[HC * NN];
__device__ float g_cat[NN * HF];       // concat of head outputs
__device__ float g_Wh2[NN * F1C];      // cat @ W_att
__device__ float g_s1b[NN];
__device__ float g_s2b[NN];
__device__ float g_gc[NN * F1C];       // gc_att
__device__ float g_t1[NN * F2C];       // gc @ W1
__device__ float g_h1[NN * F2C];       // relu(adj @ t1)
__device__ float g_t2[NN * F3C];       // h1 @ W2
__device__ float g_t3[NN * F3C];       // h1 @ W3
__device__ float g_z[NN * F3C];

// ---------------- 1. build ELL adjacency (warp per row) --------------------
__global__ void k_build(const float* __restrict__ adj) {
    int warp = (blockIdx.x * blockDim.x + threadIdx.x) >> 5;
    if (warp >= NN) return;
    int lane = threadIdx.x & 31;
    const float* arow = adj + (size_t)warp * NN;
    int cnt = 0;
    for (int j0 = 0; j0 < NN; j0 += 32) {
        float v = arow[j0 + lane];
        unsigned m = __ballot_sync(0xffffffffu, v > 0.f);
        if (v > 0.f) {
            int pos = cnt + __popc(m & ((1u << lane) - 1u));
            if (pos < MAXD) g_cols[warp * MAXD + pos] = j0 + lane;
        }
        cnt += __popc(m);
    }
    if (lane == 0) g_deg[warp] = cnt < MAXD ? cnt : MAXD;
}

// ---------------- 2. repack W_heads [H][D][F1] -> [D][H*F1] ----------------
__global__ void k_repack(const float* __restrict__ W_heads) {
    int o = blockIdx.x * blockDim.x + threadIdx.x;   // < DD*HF
    int d = o >> 8;
    int r = o & 255;
    int h = r >> 6;
    int f = r & 63;
    g_Wcat[o] = W_heads[((size_t)h * DD + d) * F1C + f];
}

// ---------------- generic fp32 tiled GEMM  C[M,Ncol]=A[M,K]@B[K,Ncol] ------
// BM=BN=64, BK=16, 256 threads, 4x4 micro-tile per thread.
__device__ __forceinline__ void gemm_body(const float* __restrict__ A,
                                          const float* __restrict__ B,
                                          float* __restrict__ C,
                                          int M, int Ncol, int K) {
    __shared__ float sA[16][64];
    __shared__ float sB[16][64];
    int bm = blockIdx.y << 6, bn = blockIdx.x << 6;
    int tid = threadIdx.x;
    int ty = tid >> 4, tx = tid & 15;
    float acc[4][4] = {};
    for (int k0 = 0; k0 < K; k0 += 16) {
        int ar = tid >> 2, kq = (tid & 3) << 2;
        float4 va = *(const float4*)(A + (size_t)(bm + ar) * K + k0 + kq);
        sA[kq + 0][ar] = va.x; sA[kq + 1][ar] = va.y;
        sA[kq + 2][ar] = va.z; sA[kq + 3][ar] = va.w;
        int br = tid >> 4, nq = (tid & 15) << 2;
        float4 vb = *(const float4*)(B + (size_t)(k0 + br) * Ncol + bn + nq);
        *(float4*)&sB[br][nq] = vb;
        __syncthreads();
#pragma unroll
        for (int kk = 0; kk < 16; kk++) {
            float a0 = sA[kk][ty * 4 + 0], a1 = sA[kk][ty * 4 + 1];
            float a2 = sA[kk][ty * 4 + 2], a3 = sA[kk][ty * 4 + 3];
            float b0 = sB[kk][tx * 4 + 0], b1 = sB[kk][tx * 4 + 1];
            float b2 = sB[kk][tx * 4 + 2], b3 = sB[kk][tx * 4 + 3];
            acc[0][0] += a0 * b0; acc[0][1] += a0 * b1; acc[0][2] += a0 * b2; acc[0][3] += a0 * b3;
            acc[1][0] += a1 * b0; acc[1][1] += a1 * b1; acc[1][2] += a1 * b2; acc[1][3] += a1 * b3;
            acc[2][0] += a2 * b0; acc[2][1] += a2 * b1; acc[2][2] += a2 * b2; acc[2][3] += a2 * b3;
            acc[3][0] += a3 * b0; acc[3][1] += a3 * b1; acc[3][2] += a3 * b2; acc[3][3] += a3 * b3;
        }
        __syncthreads();
    }
#pragma unroll
    for (int i = 0; i < 4; i++) {
        float4 v = make_float4(acc[i][0], acc[i][1], acc[i][2], acc[i][3]);
        *(float4*)(C + (size_t)(bm + ty * 4 + i) * Ncol + bn + (tx << 2)) = v;
    }
}

__global__ void k_gemm1(const float* __restrict__ x) {
    gemm_body(x, g_Wcat, g_WhAll, NN, HF, DD);       // grid (4, 64)
}
__global__ void k_gemm2(const float* __restrict__ W_att) {
    gemm_body(g_cat, W_att, g_Wh2, NN, F1C, HF);     // grid (1, 64)
}

// ---------------- attention score vectors s1,s2 (warp per (g,i)) -----------
__device__ __forceinline__ void scores_body(const float* __restrict__ Wh, int ld,
                                            const float* __restrict__ a,
                                            float* __restrict__ s1,
                                            float* __restrict__ s2, int G) {
    int w = (blockIdx.x * blockDim.x + threadIdx.x) >> 5;
    if (w >= G * NN) return;
    int g = w / NN, i = w & (NN - 1);
    int lane = threadIdx.x & 31;
    const float* whrow = Wh + (size_t)i * ld + g * F1C;
    const float* ag = a + g * 2 * F1C;
    float v1 = whrow[lane] * ag[lane] + whrow[lane + 32] * ag[lane + 32];
    float v2 = whrow[lane] * ag[64 + lane] + whrow[lane + 32] * ag[96 + lane];
#pragma unroll
    for (int o = 16; o; o >>= 1) {
        v1 += __shfl_xor_sync(0xffffffffu, v1, o);
        v2 += __shfl_xor_sync(0xffffffffu, v2, o);
    }
    if (lane == 0) { s1[g * NN + i] = v1; s2[g * NN + i] = v2; }
}

__global__ void k_scores1(const float* __restrict__ a_heads) {
    scores_body(g_WhAll, HF, a_heads, g_s1h, g_s2h, HC);
}
__global__ void k_scores2(const float* __restrict__ a_att) {
    scores_body(g_Wh2, F1C, a_att, g_s1b, g_s2b, 1);
}

// ---------------- sparse GAT: softmax over neighbors + aggregate + ELU -----
// block per row; blockDim = G*64. out[i][g*64+f], ld = G*64.
__device__ __forceinline__ void gat_body(const float* __restrict__ Wh,
                                         const float* __restrict__ s1,
                                         const float* __restrict__ s2,
                                         int G, float* __restrict__ outp) {
    __shared__ int   sc[MAXD];
    __shared__ float se[MAXD];
    __shared__ float sw[HC * MAXD];
    __shared__ float sred;
    int row = blockIdx.x;
    int tid = threadIdx.x;
    int nt = blockDim.x;
    int deg = g_deg[row];
    for (int j = tid; j < deg; j += nt) sc[j] = g_cols[row * MAXD + j];
    __syncthreads();
    for (int g = 0; g < G; g++) {
        float s1i = s1[g * NN + row];
        for (int j = tid; j < deg; j += nt) {
            float e = s1i + s2[g * NN + sc[j]];
            se[j] = e >= 0.f ? e : 0.2f * e;       // leaky_relu(0.2)
        }
        __syncthreads();
        if (tid < 32) {                             // max reduce
            float m = -1e30f;
            for (int j = tid; j < deg; j += 32) m = fmaxf(m, se[j]);
#pragma unroll
            for (int o = 16; o; o >>= 1) m = fmaxf(m, __shfl_xor_sync(0xffffffffu, m, o));
            if (tid == 0) sred = m;
        }
        __syncthreads();
        float mm = sred;
        for (int j = tid; j < deg; j += nt) se[j] = expf(se[j] - mm);
        __syncthreads();
        if (tid < 32) {                             // sum reduce
            float s = 0.f;
            for (int j = tid; j < deg; j += 32) s += se[j];
#pragma unroll
            for (int o = 16; o; o >>= 1) s += __shfl_xor_sync(0xffffffffu, s, o);
            if (tid == 0) sred = s;
        }
        __syncthreads();
        float inv = 1.f / sred;
        for (int j = tid; j < deg; j += nt) sw[g * MAXD + j] = se[j] * inv;
        __syncthreads();
    }
    // aggregation: thread (g,f) gathers Wh rows (coalesced 256*G bytes/neighbor)
    int g = tid >> 6, f = tid & 63;
    int ld = G * F1C;
    float acc = 0.f;
    for (int j = 0; j < deg; j++)
        acc += sw[g * MAXD + j] * Wh[(size_t)sc[j] * ld + g * F1C + f];
    outp[(size_t)row * ld + g * F1C + f] = acc > 0.f ? acc : expm1f(acc);  // ELU
}

__global__ void k_gat1() { gat_body(g_WhAll, g_s1h, g_s2h, HC, g_cat); }
__global__ void k_gat2() { gat_body(g_Wh2, g_s1b, g_s2b, 1, g_gc); }

// ---------------- t1 = gc @ W1  (64 -> 32) ---------------------------------
__global__ void k_fc1(const float* __restrict__ W1) {
    __shared__ float w[F1C * F2C];
    int tid = threadIdx.x;
    for (int k = tid; k < F1C * F2C; k += 256) w[k] = W1[k];
    __syncthreads();
    int idx = blockIdx.x * 256 + tid;               // over NN*F2C
    int i = idx >> 5, f = idx & 31;
    float acc = 0.f;
#pragma unroll 8
    for (int k = 0; k < F1C; k++) acc += g_gc[i * F1C + k] * w[k * F2C + f];
    g_t1[idx] = acc;
}

// ---------------- h1 = relu(adj @ t1)  (warp per row) ----------------------
__global__ void k_spmm_relu() {
    int row = (blockIdx.x * blockDim.x + threadIdx.x) >> 5;
    if (row >= NN) return;
    int f = threadIdx.x & 31;
    int deg = g_deg[row];
    const int* cp = g_cols + row * MAXD;
    float acc = 0.f;
    for (int j = 0; j < deg; j++) acc += g_t1[cp[j] * F2C + f];
    g_h1[row * F2C + f] = fmaxf(acc, 0.f);
}

// ---------------- t2 = h1@W2, t3 = h1@W3 -----------------------------------
__global__ void k_fc23(const float* __restrict__ W2, const float* __restrict__ W3) {
    __shared__ float w2[F2C * F3C], w3[F2C * F3C];
    int tid = threadIdx.x;
    for (int k = tid; k < F2C * F3C; k += 256) { w2[k] = W2[k]; w3[k] = W3[k]; }
    __syncthreads();
    int idx = blockIdx.x * 256 + tid;               // over NN*F3C
    int i = idx >> 4, f = idx & 15;
    float a2 = 0.f, a3 = 0.f;
#pragma unroll 8
    for (int k = 0; k < F2C; k++) {
        float h = g_h1[i * F2C + k];
        a2 += h * w2[k * F3C + f];
        a3 += h * w3[k * F3C + f];
    }
    g_t2[idx] = a2;
    g_t3[idx] = a3;
}

// ---------------- mu/logvar spmm + reparameterize --------------------------
__global__ void k_spmm_reparam(const float* __restrict__ eps,
                               float* __restrict__ out_mu,
                               float* __restrict__ out_lv) {
    int tid = threadIdx.x;
    int row = blockIdx.x * 16 + (tid >> 4);
    int f = tid & 15;
    int deg = g_deg[row];
    const int* cp = g_cols + row * MAXD;
    float mu = 0.f, lv = 0.f;
    for (int j = 0; j < deg; j++) {
        int c = cp[j];
        mu += g_t2[c * F3C + f];
        lv += g_t3[c * F3C + f];
    }
    int o = row * F3C + f;
    out_mu[o] = mu;
    out_lv[o] = lv;
    g_z[o] = eps[o] * expf(lv) + mu;               // reparameterize
}

// ---------------- adj_rec = z @ z^T  (64x64 tile, K=16, write-bound) -------
__global__ void k_zzT(float* __restrict__ out) {
    __shared__ float sa[64][17];
    __shared__ float sb[64][17];
    int bi = blockIdx.y << 6, bj = blockIdx.x << 6;
    int tid = threadIdx.x;
    int r = tid >> 2, q = (tid & 3) << 2;
    float4 va = *(const float4*)(g_z + ((bi + r) << 4) + q);
    sa[r][q + 0] = va.x; sa[r][q + 1] = va.y; sa[r][q + 2] = va.z; sa[r][q + 3] = va.w;
    float4 vb = *(const float4*)(g_z + ((bj + r) << 4) + q);
    sb[r][q + 0] = vb.x; sb[r][q + 1] = vb.y; sb[r][q + 2] = vb.z; sb[r][q + 3] = vb.w;
    __syncthreads();
    int ty = tid >> 4, tx = tid & 15;
    float acc[4][4] = {};
#pragma unroll
    for (int k = 0; k < 16; k++) {
        float a0 = sa[ty * 4 + 0][k], a1 = sa[ty * 4 + 1][k];
        float a2 = sa[ty * 4 + 2][k], a3 = sa[ty * 4 + 3][k];
        float b0 = sb[tx * 4 + 0][k], b1 = sb[tx * 4 + 1][k];
        float b2 = sb[tx * 4 + 2][k], b3 = sb[tx * 4 + 3][k];
        acc[0][0] += a0 * b0; acc[0][1] += a0 * b1; acc[0][2] += a0 * b2; acc[0][3] += a0 * b3;
        acc[1][0] += a1 * b0; acc[1][1] += a1 * b1; acc[1][2] += a1 * b2; acc[1][3] += a1 * b3;
        acc[2][0] += a2 * b0; acc[2][1] += a2 * b1; acc[2][2] += a2 * b2; acc[2][3] += a2 * b3;
        acc[3][0] += a3 * b0; acc[3][1] += a3 * b1; acc[3][2] += a3 * b2; acc[3][3] += a3 * b3;
    }
#pragma unroll
    for (int i = 0; i < 4; i++) {
        float4 v = make_float4(acc[i][0], acc[i][1], acc[i][2], acc[i][3]);
        *(float4*)(out + (size_t)(bi + ty * 4 + i) * NN + bj + (tx << 2)) = v;
    }
}

// ---------------- launch ----------------------------------------------------
extern "C" void kernel_launch(void* const* d_in, const int* in_sizes, int n_in,
                              void* d_out, int out_size) {
    const float* x       = (const float*)d_in[0];
    const float* adj     = (const float*)d_in[1];
    const float* W_heads = (const float*)d_in[2];
    const float* a_heads = (const float*)d_in[3];
    const float* W_att   = (const float*)d_in[4];
    const float* a_att   = (const float*)d_in[5];
    const float* W1      = (const float*)d_in[6];
    const float* W2      = (const float*)d_in[7];
    const float* W3      = (const float*)d_in[8];
    const float* eps     = (const float*)d_in[9];
    float* out = (float*)d_out;
    float* out_mu = out + (size_t)NN * NN;
    float* out_lv = out_mu + (size_t)NN * F3C;

    k_build<<<NN / 8, 256>>>(adj);                       // 4096 warps
    k_repack<<<(DD * HF) / 256, 256>>>(W_heads);
    k_gemm1<<<dim3(HF / 64, NN / 64), 256>>>(x);         // x @ Wcat
    k_scores1<<<(HC * NN) / 8, 256>>>(a_heads);
    k_gat1<<<NN, HC * 64>>>();                           // 4-head GAT -> cat
    k_gemm2<<<dim3(1, NN / 64), 256>>>(W_att);           // cat @ W_att
    k_scores2<<<NN / 8, 256>>>(a_att);
    k_gat2<<<NN, 64>>>();                                // att GAT -> gc
    k_fc1<<<(NN * F2C) / 256, 256>>>(W1);
    k_spmm_relu<<<NN / 8, 256>>>();
    k_fc23<<<(NN * F3C) / 256, 256>>>(W2, W3);
    k_spmm_reparam<<<NN / 16, 256>>>(eps, out_mu, out_lv);
    k_zzT<<<dim3(NN / 64, NN / 64), 256>>>(out);
}

// round 3
// speedup vs baseline: 1.1512x; 1.1512x over previous
#include <cuda_runtime.h>
#include <math.h>

#define NN   4096
#define DD   512
#define F1C  64
#define HC   4
#define HF   256   // HC*F1C
#define F2C  32
#define F3C  16
#define MAXD 128

// ---------------- scratch (device globals; no allocation allowed) ----------
__device__ int   g_deg[NN];
__device__ int   g_cols[NN * MAXD];
__device__ float g_WhAll[NN * HF];     // Wh for 4 heads, [i][h*64+f]
__device__ float g_s1h[HC * NN];
__device__ float g_s2h[HC * NN];
__device__ float g_cat[NN * HF];       // concat of head outputs
__device__ float g_Wh2[NN * F1C];      // cat @ W_att
__device__ float g_s1b[NN];
__device__ float g_s2b[NN];
__device__ float g_t1[NN * F2C];       // gc_att @ W1
__device__ float g_t2[NN * F3C];       // h1 @ W2
__device__ float g_t3[NN * F3C];       // h1 @ W3
__device__ float g_z[NN * F3C];

// ---------------- 1. build ELL adjacency (warp per row, float4) ------------
// neighbor ORDER within a row is irrelevant (set semantics for softmax/aggr).
__global__ void k_build(const float* __restrict__ adj) {
    int warp = (blockIdx.x * blockDim.x + threadIdx.x) >> 5;
    if (warp >= NN) return;
    int lane = threadIdx.x & 31;
    const float4* arow = (const float4*)(adj + (size_t)warp * NN);
    int cnt = 0;
    for (int j0 = 0; j0 < NN; j0 += 128) {
        float4 v = arow[(j0 >> 2) + lane];
        int base = j0 + lane * 4;
#pragma unroll
        for (int c = 0; c < 4; c++) {
            float val = (c == 0) ? v.x : (c == 1) ? v.y : (c == 2) ? v.z : v.w;
            unsigned m = __ballot_sync(0xffffffffu, val > 0.f);
            if (val > 0.f) {
                int pos = cnt + __popc(m & ((1u << lane) - 1u));
                if (pos < MAXD) g_cols[warp * MAXD + pos] = base + c;
            }
            cnt += __popc(m);
        }
    }
    if (lane == 0) g_deg[warp] = cnt < MAXD ? cnt : MAXD;
}

// ---------------- 2. GEMM1: Wh = x @ W_heads (per-head), + score epilogue --
// 64x64 tile, BK=16, 256 threads, 4x4 micro. blockIdx.x = head.
__global__ void k_gemm1(const float* __restrict__ x,
                        const float* __restrict__ W_heads,
                        const float* __restrict__ a_heads) {
    __shared__ float sA[16][64];
    __shared__ float sB[16][64];
    int head = blockIdx.x;
    int bm = blockIdx.y << 6;
    int tid = threadIdx.x;
    int ty = tid >> 4, tx = tid & 15;
    const float* B = W_heads + (size_t)head * DD * F1C;
    float acc[4][4] = {};
    for (int k0 = 0; k0 < DD; k0 += 16) {
        int ar = tid >> 2, kq = (tid & 3) << 2;
        float4 va = *(const float4*)(x + (size_t)(bm + ar) * DD + k0 + kq);
        sA[kq + 0][ar] = va.x; sA[kq + 1][ar] = va.y;
        sA[kq + 2][ar] = va.z; sA[kq + 3][ar] = va.w;
        int br = tid >> 4, nq = (tid & 15) << 2;
        *(float4*)&sB[br][nq] = *(const float4*)(B + (size_t)(k0 + br) * F1C + nq);
        __syncthreads();
#pragma unroll
        for (int kk = 0; kk < 16; kk++) {
            float a0 = sA[kk][ty * 4 + 0], a1 = sA[kk][ty * 4 + 1];
            float a2 = sA[kk][ty * 4 + 2], a3 = sA[kk][ty * 4 + 3];
            float b0 = sB[kk][tx * 4 + 0], b1 = sB[kk][tx * 4 + 1];
            float b2 = sB[kk][tx * 4 + 2], b3 = sB[kk][tx * 4 + 3];
            acc[0][0] += a0 * b0; acc[0][1] += a0 * b1; acc[0][2] += a0 * b2; acc[0][3] += a0 * b3;
            acc[1][0] += a1 * b0; acc[1][1] += a1 * b1; acc[1][2] += a1 * b2; acc[1][3] += a1 * b3;
            acc[2][0] += a2 * b0; acc[2][1] += a2 * b1; acc[2][2] += a2 * b2; acc[2][3] += a2 * b3;
            acc[3][0] += a3 * b0; acc[3][1] += a3 * b1; acc[3][2] += a3 * b2; acc[3][3] += a3 * b3;
        }
        __syncthreads();
    }
#pragma unroll
    for (int i = 0; i < 4; i++) {
        float4 v = make_float4(acc[i][0], acc[i][1], acc[i][2], acc[i][3]);
        *(float4*)(g_WhAll + (size_t)(bm + ty * 4 + i) * HF + head * F1C + (tx << 2)) = v;
    }
    // score epilogue: s1[i] = Wh_row . a[:64], s2[i] = Wh_row . a[64:]
    const float* ag = a_heads + head * 2 * F1C;
    float a1v[4], a2v[4];
#pragma unroll
    for (int c = 0; c < 4; c++) { a1v[c] = ag[(tx << 2) + c]; a2v[c] = ag[F1C + (tx << 2) + c]; }
#pragma unroll
    for (int i = 0; i < 4; i++) {
        float p1 = acc[i][0] * a1v[0] + acc[i][1] * a1v[1] + acc[i][2] * a1v[2] + acc[i][3] * a1v[3];
        float p2 = acc[i][0] * a2v[0] + acc[i][1] * a2v[1] + acc[i][2] * a2v[2] + acc[i][3] * a2v[3];
#pragma unroll
        for (int o = 8; o; o >>= 1) {
            p1 += __shfl_xor_sync(0xffffffffu, p1, o);
            p2 += __shfl_xor_sync(0xffffffffu, p2, o);
        }
        if (tx == 0) {
            int row = bm + ty * 4 + i;
            g_s1h[head * NN + row] = p1;
            g_s2h[head * NN + row] = p2;
        }
    }
}

// ---------------- GEMM2: Wh2 = cat @ W_att, + score epilogue ---------------
__global__ void k_gemm2(const float* __restrict__ W_att,
                        const float* __restrict__ a_att) {
    __shared__ float sA[16][64];
    __shared__ float sB[16][64];
    int bm = blockIdx.y << 6;
    int tid = threadIdx.x;
    int ty = tid >> 4, tx = tid & 15;
    float acc[4][4] = {};
    for (int k0 = 0; k0 < HF; k0 += 16) {
        int ar = tid >> 2, kq = (tid & 3) << 2;
        float4 va = *(const float4*)(g_cat + (size_t)(bm + ar) * HF + k0 + kq);
        sA[kq + 0][ar] = va.x; sA[kq + 1][ar] = va.y;
        sA[kq + 2][ar] = va.z; sA[kq + 3][ar] = va.w;
        int br = tid >> 4, nq = (tid & 15) << 2;
        *(float4*)&sB[br][nq] = *(const float4*)(W_att + (size_t)(k0 + br) * F1C + nq);
        __syncthreads();
#pragma unroll
        for (int kk = 0; kk < 16; kk++) {
            float a0 = sA[kk][ty * 4 + 0], a1 = sA[kk][ty * 4 + 1];
            float a2 = sA[kk][ty * 4 + 2], a3 = sA[kk][ty * 4 + 3];
            float b0 = sB[kk][tx * 4 + 0], b1 = sB[kk][tx * 4 + 1];
            float b2 = sB[kk][tx * 4 + 2], b3 = sB[kk][tx * 4 + 3];
            acc[0][0] += a0 * b0; acc[0][1] += a0 * b1; acc[0][2] += a0 * b2; acc[0][3] += a0 * b3;
            acc[1][0] += a1 * b0; acc[1][1] += a1 * b1; acc[1][2] += a1 * b2; acc[1][3] += a1 * b3;
            acc[2][0] += a2 * b0; acc[2][1] += a2 * b1; acc[2][2] += a2 * b2; acc[2][3] += a2 * b3;
            acc[3][0] += a3 * b0; acc[3][1] += a3 * b1; acc[3][2] += a3 * b2; acc[3][3] += a3 * b3;
        }
        __syncthreads();
    }
#pragma unroll
    for (int i = 0; i < 4; i++) {
        float4 v = make_float4(acc[i][0], acc[i][1], acc[i][2], acc[i][3]);
        *(float4*)(g_Wh2 + (size_t)(bm + ty * 4 + i) * F1C + (tx << 2)) = v;
    }
    float a1v[4], a2v[4];
#pragma unroll
    for (int c = 0; c < 4; c++) { a1v[c] = a_att[(tx << 2) + c]; a2v[c] = a_att[F1C + (tx << 2) + c]; }
#pragma unroll
    for (int i = 0; i < 4; i++) {
        float p1 = acc[i][0] * a1v[0] + acc[i][1] * a1v[1] + acc[i][2] * a1v[2] + acc[i][3] * a1v[3];
        float p2 = acc[i][0] * a2v[0] + acc[i][1] * a2v[1] + acc[i][2] * a2v[2] + acc[i][3] * a2v[3];
#pragma unroll
        for (int o = 8; o; o >>= 1) {
            p1 += __shfl_xor_sync(0xffffffffu, p1, o);
            p2 += __shfl_xor_sync(0xffffffffu, p2, o);
        }
        if (tx == 0) {
            int row = bm + ty * 4 + i;
            g_s1b[row] = p1;
            g_s2b[row] = p2;
        }
    }
}

// ---------------- GAT1: warp-per-head softmax + block aggregation + ELU ----
__global__ void k_gat1() {
    __shared__ int   sc[MAXD];
    __shared__ float sw[HC * MAXD];
    __shared__ float sinv[HC];
    int row = blockIdx.x;
    int tid = threadIdx.x;
    int deg = g_deg[row];
    for (int j = tid; j < deg; j += 256) sc[j] = g_cols[row * MAXD + j];
    __syncthreads();
    int wid = tid >> 5, lane = tid & 31;
    if (wid < HC) {
        int g = wid;
        float s1i = g_s1h[g * NN + row];
        float m = -1e30f;
        for (int j = lane; j < deg; j += 32) {
            float e = s1i + g_s2h[g * NN + sc[j]];
            e = e >= 0.f ? e : 0.2f * e;             // leaky_relu(0.2)
            sw[g * MAXD + j] = e;
            m = fmaxf(m, e);
        }
#pragma unroll
        for (int o = 16; o; o >>= 1) m = fmaxf(m, __shfl_xor_sync(0xffffffffu, m, o));
        float s = 0.f;
        for (int j = lane; j < deg; j += 32) {
            float w = expf(sw[g * MAXD + j] - m);
            sw[g * MAXD + j] = w;
            s += w;
        }
#pragma unroll
        for (int o = 16; o; o >>= 1) s += __shfl_xor_sync(0xffffffffu, s, o);
        if (lane == 0) sinv[g] = 1.f / s;
    }
    __syncthreads();
    int g = tid >> 6, f = tid & 63;
    const float* base = g_WhAll + g * F1C + f;
    float acc = 0.f;
    for (int j = 0; j < deg; j++)
        acc += sw[g * MAXD + j] * base[(size_t)sc[j] * HF];
    acc *= sinv[g];
    g_cat[(size_t)row * HF + g * F1C + f] = acc > 0.f ? acc : expm1f(acc);   // ELU
}

// ---------------- GAT2 + fc1: gc = GAT(cat path); t1 = gc @ W1 -------------
__global__ void k_gat2_fc1(const float* __restrict__ W1) {
    __shared__ int   sc[MAXD];
    __shared__ float sw[MAXD];
    __shared__ float sinv1;
    __shared__ float sgc[F1C];
    int row = blockIdx.x;
    int tid = threadIdx.x;   // blockDim = 64
    int deg = g_deg[row];
    for (int j = tid; j < deg; j += 64) sc[j] = g_cols[row * MAXD + j];
    __syncthreads();
    if (tid < 32) {
        int lane = tid;
        float s1i = g_s1b[row];
        float m = -1e30f;
        for (int j = lane; j < deg; j += 32) {
            float e = s1i + g_s2b[sc[j]];
            e = e >= 0.f ? e : 0.2f * e;
            sw[j] = e;
            m = fmaxf(m, e);
        }
#pragma unroll
        for (int o = 16; o; o >>= 1) m = fmaxf(m, __shfl_xor_sync(0xffffffffu, m, o));
        float s = 0.f;
        for (int j = lane; j < deg; j += 32) {
            float w = expf(sw[j] - m);
            sw[j] = w;
            s += w;
        }
#pragma unroll
        for (int o = 16; o; o >>= 1) s += __shfl_xor_sync(0xffffffffu, s, o);
        if (lane == 0) sinv1 = 1.f / s;
    }
    __syncthreads();
    float acc = 0.f;
    const float* base = g_Wh2 + tid;
    for (int j = 0; j < deg; j++)
        acc += sw[j] * base[(size_t)sc[j] * F1C];
    acc *= sinv1;
    sgc[tid] = acc > 0.f ? acc : expm1f(acc);        // ELU
    __syncthreads();
    if (tid < F2C) {
        float t = 0.f;
#pragma unroll 16
        for (int k = 0; k < F1C; k++) t += sgc[k] * W1[k * F2C + tid];
        g_t1[row * F2C + tid] = t;
    }
}

// ---------------- h1 = relu(adj@t1) fused with t2=h1@W2, t3=h1@W3 ----------
__global__ void k_spmm_fc23(const float* __restrict__ W2,
                            const float* __restrict__ W3) {
    __shared__ float sh[8][F2C];
    __shared__ float w2[F2C * F3C], w3[F2C * F3C];
    int tid = threadIdx.x;                            // 256 threads
    for (int k = tid; k < F2C * F3C; k += 256) { w2[k] = W2[k]; w3[k] = W3[k]; }
    int wid = tid >> 5, lane = tid & 31;
    int row = blockIdx.x * 8 + wid;
    int deg = g_deg[row];
    const int* cp = g_cols + row * MAXD;
    float a = 0.f;
    for (int j = 0; j < deg; j++) a += g_t1[cp[j] * F2C + lane];
    sh[wid][lane] = fmaxf(a, 0.f);
    __syncthreads();
    int r = tid >> 5, o = tid & 31, f = o & 15;
    const float* w = (o < 16) ? w2 : w3;
    float v = 0.f;
#pragma unroll 8
    for (int k = 0; k < F2C; k++) v += sh[r][k] * w[k * F3C + f];
    float* dst = (o < 16) ? g_t2 : g_t3;
    dst[(blockIdx.x * 8 + r) * F3C + f] = v;
}

// ---------------- mu/logvar spmm + reparameterize --------------------------
__global__ void k_spmm_reparam(const float* __restrict__ eps,
                               float* __restrict__ out_mu,
                               float* __restrict__ out_lv) {
    int tid = threadIdx.x;
    int row = blockIdx.x * 16 + (tid >> 4);
    int f = tid & 15;
    int deg = g_deg[row];
    const int* cp = g_cols + row * MAXD;
    float mu = 0.f, lv = 0.f;
    for (int j = 0; j < deg; j++) {
        int c = cp[j];
        mu += g_t2[c * F3C + f];
        lv += g_t3[c * F3C + f];
    }
    int o = row * F3C + f;
    out_mu[o] = mu;
    out_lv[o] = lv;
    g_z[o] = eps[o] * expf(lv) + mu;
}

// ---------------- adj_rec = z @ z^T (64x64 tile, K=16, write-bound) --------
__global__ void k_zzT(float* __restrict__ out) {
    __shared__ float sa[64][17];
    __shared__ float sb[64][17];
    int bi = blockIdx.y << 6, bj = blockIdx.x << 6;
    int tid = threadIdx.x;
    int r = tid >> 2, q = (tid & 3) << 2;
    float4 va = *(const float4*)(g_z + ((bi + r) << 4) + q);
    sa[r][q + 0] = va.x; sa[r][q + 1] = va.y; sa[r][q + 2] = va.z; sa[r][q + 3] = va.w;
    float4 vb = *(const float4*)(g_z + ((bj + r) << 4) + q);
    sb[r][q + 0] = vb.x; sb[r][q + 1] = vb.y; sb[r][q + 2] = vb.z; sb[r][q + 3] = vb.w;
    __syncthreads();
    int ty = tid >> 4, tx = tid & 15;
    float acc[4][4] = {};
#pragma unroll
    for (int k = 0; k < 16; k++) {
        float a0 = sa[ty * 4 + 0][k], a1 = sa[ty * 4 + 1][k];
        float a2 = sa[ty * 4 + 2][k], a3 = sa[ty * 4 + 3][k];
        float b0 = sb[tx * 4 + 0][k], b1 = sb[tx * 4 + 1][k];
        float b2 = sb[tx * 4 + 2][k], b3 = sb[tx * 4 + 3][k];
        acc[0][0] += a0 * b0; acc[0][1] += a0 * b1; acc[0][2] += a0 * b2; acc[0][3] += a0 * b3;
        acc[1][0] += a1 * b0; acc[1][1] += a1 * b1; acc[1][2] += a1 * b2; acc[1][3] += a1 * b3;
        acc[2][0] += a2 * b0; acc[2][1] += a2 * b1; acc[2][2] += a2 * b2; acc[2][3] += a2 * b3;
        acc[3][0] += a3 * b0; acc[3][1] += a3 * b1; acc[3][2] += a3 * b2; acc[3][3] += a3 * b3;
    }
#pragma unroll
    for (int i = 0; i < 4; i++) {
        float4 v = make_float4(acc[i][0], acc[i][1], acc[i][2], acc[i][3]);
        *(float4*)(out + (size_t)(bi + ty * 4 + i) * NN + bj + (tx << 2)) = v;
    }
}

// ---------------- launch ----------------------------------------------------
extern "C" void kernel_launch(void* const* d_in, const int* in_sizes, int n_in,
                              void* d_out, int out_size) {
    const float* x       = (const float*)d_in[0];
    const float* adj     = (const float*)d_in[1];
    const float* W_heads = (const float*)d_in[2];
    const float* a_heads = (const float*)d_in[3];
    const float* W_att   = (const float*)d_in[4];
    const float* a_att   = (const float*)d_in[5];
    const float* W1      = (const float*)d_in[6];
    const float* W2      = (const float*)d_in[7];
    const float* W3      = (const float*)d_in[8];
    const float* eps     = (const float*)d_in[9];
    float* out = (float*)d_out;
    float* out_mu = out + (size_t)NN * NN;
    float* out_lv = out_mu + (size_t)NN * F3C;

    k_build<<<NN / 8, 256>>>(adj);
    k_gemm1<<<dim3(HC, NN / 64), 256>>>(x, W_heads, a_heads);
    k_gat1<<<NN, 256>>>();
    k_gemm2<<<dim3(1, NN / 64), 256>>>(W_att, a_att);
    k_gat2_fc1<<<NN, 64>>>(W1);
    k_spmm_fc23<<<NN / 8, 256>>>(W2, W3);
    k_spmm_reparam<<<NN / 16, 256>>>(eps, out_mu, out_lv);
    k_zzT<<<dim3(NN / 64, NN / 64), 256>>>(out);
}

// round 4
// speedup vs baseline: 1.2399x; 1.0771x over previous
#include <cuda_runtime.h>
#include <math.h>

#define NN   4096
#define DD   512
#define F1C  64
#define HC   4
#define HF   256   // HC*F1C
#define F2C  32
#define F3C  16
#define MAXD 128

// ---------------- scratch (device globals; no allocation allowed) ----------
__device__ int   g_deg[NN];
__device__ int   g_cols[NN * MAXD];
__device__ float g_WhAll[NN * HF];     // Wh for 4 heads, [i][h*64+f]
__device__ float g_s1h[HC * NN];
__device__ float g_s2h[HC * NN];
__device__ float g_cat[NN * HF];       // concat of head outputs
__device__ float g_Wh2[NN * F1C];      // cat @ W_att
__device__ float g_s1b[NN];
__device__ float g_s2b[NN];
__device__ float g_t1[NN * F2C];       // gc_att @ W1
__device__ float g_t2[NN * F3C];       // h1 @ W2
__device__ float g_t3[NN * F3C];       // h1 @ W3
__device__ float g_z[NN * F3C];

// ============ fused: blocks [0,256) do GEMM1 tiles, [256,768) build ELL =====
// GEMM1 (x @ W_heads per head + score epilogue) is FMA-bound; the adjacency
// scan is DRAM-bound; they are independent, so co-scheduling them overlaps
// the 67MB adj read under the GEMM.
__global__ void k_build_gemm1(const float* __restrict__ adj,
                              const float* __restrict__ x,
                              const float* __restrict__ W_heads,
                              const float* __restrict__ a_heads) {
    __shared__ float sA[16][64];
    __shared__ float sB[16][64];
    int bx = blockIdx.x;
    if (bx >= 256) {
        // ---- adjacency build: warp per row (float4 scan + ballot compact) --
        int wb = bx - 256;
        int row = wb * 8 + (threadIdx.x >> 5);
        int lane = threadIdx.x & 31;
        const float4* arow = (const float4*)(adj + (size_t)row * NN);
        int cnt = 0;
        for (int j0 = 0; j0 < NN; j0 += 128) {
            float4 v = arow[(j0 >> 2) + lane];
            int base = j0 + lane * 4;
#pragma unroll
            for (int c = 0; c < 4; c++) {
                float val = (c == 0) ? v.x : (c == 1) ? v.y : (c == 2) ? v.z : v.w;
                unsigned m = __ballot_sync(0xffffffffu, val > 0.f);
                if (val > 0.f) {
                    int pos = cnt + __popc(m & ((1u << lane) - 1u));
                    if (pos < MAXD) g_cols[row * MAXD + pos] = base + c;
                }
                cnt += __popc(m);
            }
        }
        if (lane == 0) g_deg[row] = cnt < MAXD ? cnt : MAXD;
        return;
    }
    // ---- GEMM1 tile: head = bx>>6, row-block = bx&63 -----------------------
    int head = bx >> 6;
    int bm = (bx & 63) << 6;
    int tid = threadIdx.x;
    int ty = tid >> 4, tx = tid & 15;
    const float* B = W_heads + (size_t)head * DD * F1C;
    float acc[4][4] = {};
    for (int k0 = 0; k0 < DD; k0 += 16) {
        int ar = tid >> 2, kq = (tid & 3) << 2;
        float4 va = *(const float4*)(x + (size_t)(bm + ar) * DD + k0 + kq);
        sA[kq + 0][ar] = va.x; sA[kq + 1][ar] = va.y;
        sA[kq + 2][ar] = va.z; sA[kq + 3][ar] = va.w;
        int br = tid >> 4, nq = (tid & 15) << 2;
        *(float4*)&sB[br][nq] = *(const float4*)(B + (size_t)(k0 + br) * F1C + nq);
        __syncthreads();
#pragma unroll
        for (int kk = 0; kk < 16; kk++) {
            float a0 = sA[kk][ty * 4 + 0], a1 = sA[kk][ty * 4 + 1];
            float a2 = sA[kk][ty * 4 + 2], a3 = sA[kk][ty * 4 + 3];
            float b0 = sB[kk][tx * 4 + 0], b1 = sB[kk][tx * 4 + 1];
            float b2 = sB[kk][tx * 4 + 2], b3 = sB[kk][tx * 4 + 3];
            acc[0][0] += a0 * b0; acc[0][1] += a0 * b1; acc[0][2] += a0 * b2; acc[0][3] += a0 * b3;
            acc[1][0] += a1 * b0; acc[1][1] += a1 * b1; acc[1][2] += a1 * b2; acc[1][3] += a1 * b3;
            acc[2][0] += a2 * b0; acc[2][1] += a2 * b1; acc[2][2] += a2 * b2; acc[2][3] += a2 * b3;
            acc[3][0] += a3 * b0; acc[3][1] += a3 * b1; acc[3][2] += a3 * b2; acc[3][3] += a3 * b3;
        }
        __syncthreads();
    }
#pragma unroll
    for (int i = 0; i < 4; i++) {
        float4 v = make_float4(acc[i][0], acc[i][1], acc[i][2], acc[i][3]);
        *(float4*)(g_WhAll + (size_t)(bm + ty * 4 + i) * HF + head * F1C + (tx << 2)) = v;
    }
    // score epilogue
    const float* ag = a_heads + head * 2 * F1C;
    float a1v[4], a2v[4];
#pragma unroll
    for (int c = 0; c < 4; c++) { a1v[c] = ag[(tx << 2) + c]; a2v[c] = ag[F1C + (tx << 2) + c]; }
#pragma unroll
    for (int i = 0; i < 4; i++) {
        float p1 = acc[i][0] * a1v[0] + acc[i][1] * a1v[1] + acc[i][2] * a1v[2] + acc[i][3] * a1v[3];
        float p2 = acc[i][0] * a2v[0] + acc[i][1] * a2v[1] + acc[i][2] * a2v[2] + acc[i][3] * a2v[3];
#pragma unroll
        for (int o = 8; o; o >>= 1) {
            p1 += __shfl_xor_sync(0xffffffffu, p1, o);
            p2 += __shfl_xor_sync(0xffffffffu, p2, o);
        }
        if (tx == 0) {
            int row = bm + ty * 4 + i;
            g_s1h[head * NN + row] = p1;
            g_s2h[head * NN + row] = p2;
        }
    }
}

// ---------------- GAT1: warp-per-head softmax + block aggregation + ELU ----
__global__ void k_gat1() {
    __shared__ int   sc[MAXD];
    __shared__ float sw[HC * MAXD];
    __shared__ float sinv[HC];
    int row = blockIdx.x;
    int tid = threadIdx.x;
    int deg = g_deg[row];
    for (int j = tid; j < deg; j += 256) sc[j] = g_cols[row * MAXD + j];
    __syncthreads();
    int wid = tid >> 5, lane = tid & 31;
    if (wid < HC) {
        int g = wid;
        float s1i = g_s1h[g * NN + row];
        float m = -1e30f;
        for (int j = lane; j < deg; j += 32) {
            float e = s1i + g_s2h[g * NN + sc[j]];
            e = e >= 0.f ? e : 0.2f * e;             // leaky_relu(0.2)
            sw[g * MAXD + j] = e;
            m = fmaxf(m, e);
        }
#pragma unroll
        for (int o = 16; o; o >>= 1) m = fmaxf(m, __shfl_xor_sync(0xffffffffu, m, o));
        float s = 0.f;
        for (int j = lane; j < deg; j += 32) {
            float w = expf(sw[g * MAXD + j] - m);
            sw[g * MAXD + j] = w;
            s += w;
        }
#pragma unroll
        for (int o = 16; o; o >>= 1) s += __shfl_xor_sync(0xffffffffu, s, o);
        if (lane == 0) sinv[g] = 1.f / s;
    }
    __syncthreads();
    int g = tid >> 6, f = tid & 63;
    const float* base = g_WhAll + g * F1C + f;
    const float* wp = sw + g * MAXD;
    float ac0 = 0.f, ac1 = 0.f, ac2 = 0.f, ac3 = 0.f;
    int j = 0;
    for (; j + 4 <= deg; j += 4) {
        ac0 += wp[j + 0] * base[(size_t)sc[j + 0] * HF];
        ac1 += wp[j + 1] * base[(size_t)sc[j + 1] * HF];
        ac2 += wp[j + 2] * base[(size_t)sc[j + 2] * HF];
        ac3 += wp[j + 3] * base[(size_t)sc[j + 3] * HF];
    }
    for (; j < deg; j++) ac0 += wp[j] * base[(size_t)sc[j] * HF];
    float acc = ((ac0 + ac1) + (ac2 + ac3)) * sinv[g];
    g_cat[(size_t)row * HF + g * F1C + f] = acc > 0.f ? acc : expm1f(acc);   // ELU
}

// ---------------- GEMM2: Wh2 = cat @ W_att, BM=16 (256 CTAs) + scores ------
// grid = 256, block = 256. Thread (row=tid>>4, colq=(tid&15)*4) -> 4 outputs.
__global__ void k_gemm2(const float* __restrict__ W_att,
                        const float* __restrict__ a_att) {
    __shared__ float sA[32][17];   // transposed [k][row], padded
    __shared__ float sB[32][64];
    int bm = blockIdx.x << 4;
    int tid = threadIdx.x;
    int row = tid >> 4, cq = (tid & 15) << 2;
    float acc0 = 0.f, acc1 = 0.f, acc2 = 0.f, acc3 = 0.f;
    for (int k0 = 0; k0 < HF; k0 += 32) {
        if (tid < 128) {
            int r = tid >> 3, kq = (tid & 7) << 2;
            float4 va = *(const float4*)(g_cat + (size_t)(bm + r) * HF + k0 + kq);
            sA[kq + 0][r] = va.x; sA[kq + 1][r] = va.y;
            sA[kq + 2][r] = va.z; sA[kq + 3][r] = va.w;
        }
#pragma unroll
        for (int t = 0; t < 2; t++) {
            int idx = tid + t * 256;
            int kr = idx >> 4, bq = (idx & 15) << 2;
            *(float4*)&sB[kr][bq] = *(const float4*)(W_att + (size_t)(k0 + kr) * F1C + bq);
        }
        __syncthreads();
#pragma unroll
        for (int kk = 0; kk < 32; kk++) {
            float a = sA[kk][row];
            float4 b = *(const float4*)&sB[kk][cq];
            acc0 += a * b.x; acc1 += a * b.y; acc2 += a * b.z; acc3 += a * b.w;
        }
        __syncthreads();
    }
    float4 v = make_float4(acc0, acc1, acc2, acc3);
    *(float4*)(g_Wh2 + (size_t)(bm + row) * F1C + cq) = v;
    // scores: reduce over the 16 threads sharing this row (contiguous lanes)
    float p1 = acc0 * a_att[cq] + acc1 * a_att[cq + 1] + acc2 * a_att[cq + 2] + acc3 * a_att[cq + 3];
    float p2 = acc0 * a_att[F1C + cq] + acc1 * a_att[F1C + cq + 1]
             + acc2 * a_att[F1C + cq + 2] + acc3 * a_att[F1C + cq + 3];
#pragma unroll
    for (int o = 8; o; o >>= 1) {
        p1 += __shfl_xor_sync(0xffffffffu, p1, o);
        p2 += __shfl_xor_sync(0xffffffffu, p2, o);
    }
    if ((tid & 15) == 0) {
        g_s1b[bm + row] = p1;
        g_s2b[bm + row] = p2;
    }
}

// ---------------- GAT2 + fc1: gc = GAT(att path); t1 = gc @ W1 -------------
__global__ void k_gat2_fc1(const float* __restrict__ W1) {
    __shared__ int   sc[MAXD];
    __shared__ float sw[MAXD];
    __shared__ float sinv1;
    __shared__ float sgc[F1C];
    int row = blockIdx.x;
    int tid = threadIdx.x;   // blockDim = 64
    int deg = g_deg[row];
    for (int j = tid; j < deg; j += 64) sc[j] = g_cols[row * MAXD + j];
    __syncthreads();
    if (tid < 32) {
        int lane = tid;
        float s1i = g_s1b[row];
        float m = -1e30f;
        for (int j = lane; j < deg; j += 32) {
            float e = s1i + g_s2b[sc[j]];
            e = e >= 0.f ? e : 0.2f * e;
            sw[j] = e;
            m = fmaxf(m, e);
        }
#pragma unroll
        for (int o = 16; o; o >>= 1) m = fmaxf(m, __shfl_xor_sync(0xffffffffu, m, o));
        float s = 0.f;
        for (int j = lane; j < deg; j += 32) {
            float w = expf(sw[j] - m);
            sw[j] = w;
            s += w;
        }
#pragma unroll
        for (int o = 16; o; o >>= 1) s += __shfl_xor_sync(0xffffffffu, s, o);
        if (lane == 0) sinv1 = 1.f / s;
    }
    __syncthreads();
    const float* base = g_Wh2 + tid;
    float ac0 = 0.f, ac1 = 0.f, ac2 = 0.f, ac3 = 0.f;
    int j = 0;
    for (; j + 4 <= deg; j += 4) {
        ac0 += sw[j + 0] * base[(size_t)sc[j + 0] * F1C];
        ac1 += sw[j + 1] * base[(size_t)sc[j + 1] * F1C];
        ac2 += sw[j + 2] * base[(size_t)sc[j + 2] * F1C];
        ac3 += sw[j + 3] * base[(size_t)sc[j + 3] * F1C];
    }
    for (; j < deg; j++) ac0 += sw[j] * base[(size_t)sc[j] * F1C];
    float acc = ((ac0 + ac1) + (ac2 + ac3)) * sinv1;
    sgc[tid] = acc > 0.f ? acc : expm1f(acc);        // ELU
    __syncthreads();
    if (tid < F2C) {
        float t = 0.f;
#pragma unroll 16
        for (int k = 0; k < F1C; k++) t += sgc[k] * W1[k * F2C + tid];
        g_t1[row * F2C + tid] = t;
    }
}

// ---------------- h1 = relu(adj@t1) fused with t2=h1@W2, t3=h1@W3 ----------
__global__ void k_spmm_fc23(const float* __restrict__ W2,
                            const float* __restrict__ W3) {
    __shared__ float sh[8][F2C];
    __shared__ float w2[F2C * F3C], w3[F2C * F3C];
    int tid = threadIdx.x;                            // 256 threads
    for (int k = tid; k < F2C * F3C; k += 256) { w2[k] = W2[k]; w3[k] = W3[k]; }
    int wid = tid >> 5, lane = tid & 31;
    int row = blockIdx.x * 8 + wid;
    int deg = g_deg[row];
    const int* cp = g_cols + row * MAXD;
    float a0 = 0.f, a1 = 0.f, a2 = 0.f, a3 = 0.f;
    int j = 0;
    for (; j + 4 <= deg; j += 4) {
        a0 += g_t1[cp[j + 0] * F2C + lane];
        a1 += g_t1[cp[j + 1] * F2C + lane];
        a2 += g_t1[cp[j + 2] * F2C + lane];
        a3 += g_t1[cp[j + 3] * F2C + lane];
    }
    for (; j < deg; j++) a0 += g_t1[cp[j] * F2C + lane];
    sh[wid][lane] = fmaxf((a0 + a1) + (a2 + a3), 0.f);
    __syncthreads();
    int r = tid >> 5, o = tid & 31, f = o & 15;
    const float* w = (o < 16) ? w2 : w3;
    float v = 0.f;
#pragma unroll 8
    for (int k = 0; k < F2C; k++) v += sh[r][k] * w[k * F3C + f];
    float* dst = (o < 16) ? g_t2 : g_t3;
    dst[(blockIdx.x * 8 + r) * F3C + f] = v;
}

// ---------------- mu/logvar spmm + reparameterize --------------------------
__global__ void k_spmm_reparam(const float* __restrict__ eps,
                               float* __restrict__ out_mu,
                               float* __restrict__ out_lv) {
    int tid = threadIdx.x;
    int row = blockIdx.x * 16 + (tid >> 4);
    int f = tid & 15;
    int deg = g_deg[row];
    const int* cp = g_cols + row * MAXD;
    float m0 = 0.f, m1 = 0.f, l0 = 0.f, l1 = 0.f;
    int j = 0;
    for (; j + 2 <= deg; j += 2) {
        int c0 = cp[j], c1 = cp[j + 1];
        m0 += g_t2[c0 * F3C + f];
        l0 += g_t3[c0 * F3C + f];
        m1 += g_t2[c1 * F3C + f];
        l1 += g_t3[c1 * F3C + f];
    }
    if (j < deg) { int c = cp[j]; m0 += g_t2[c * F3C + f]; l0 += g_t3[c * F3C + f]; }
    float mu = m0 + m1, lv = l0 + l1;
    int o = row * F3C + f;
    out_mu[o] = mu;
    out_lv[o] = lv;
    g_z[o] = eps[o] * expf(lv) + mu;
}

// ---------------- adj_rec = z @ z^T (64x64 tile, K=16, write-bound) --------
__global__ void k_zzT(float* __restrict__ out) {
    __shared__ float sa[64][17];
    __shared__ float sb[64][17];
    int bi = blockIdx.y << 6, bj = blockIdx.x << 6;
    int tid = threadIdx.x;
    int r = tid >> 2, q = (tid & 3) << 2;
    float4 va = *(const float4*)(g_z + ((bi + r) << 4) + q);
    sa[r][q + 0] = va.x; sa[r][q + 1] = va.y; sa[r][q + 2] = va.z; sa[r][q + 3] = va.w;
    float4 vb = *(const float4*)(g_z + ((bj + r) << 4) + q);
    sb[r][q + 0] = vb.x; sb[r][q + 1] = vb.y; sb[r][q + 2] = vb.z; sb[r][q + 3] = vb.w;
    __syncthreads();
    int ty = tid >> 4, tx = tid & 15;
    float acc[4][4] = {};
#pragma unroll
    for (int k = 0; k < 16; k++) {
        float a0 = sa[ty * 4 + 0][k], a1 = sa[ty * 4 + 1][k];
        float a2 = sa[ty * 4 + 2][k], a3 = sa[ty * 4 + 3][k];
        float b0 = sb[tx * 4 + 0][k], b1 = sb[tx * 4 + 1][k];
        float b2 = sb[tx * 4 + 2][k], b3 = sb[tx * 4 + 3][k];
        acc[0][0] += a0 * b0; acc[0][1] += a0 * b1; acc[0][2] += a0 * b2; acc[0][3] += a0 * b3;
        acc[1][0] += a1 * b0; acc[1][1] += a1 * b1; acc[1][2] += a1 * b2; acc[1][3] += a1 * b3;
        acc[2][0] += a2 * b0; acc[2][1] += a2 * b1; acc[2][2] += a2 * b2; acc[2][3] += a2 * b3;
        acc[3][0] += a3 * b0; acc[3][1] += a3 * b1; acc[3][2] += a3 * b2; acc[3][3] += a3 * b3;
    }
#pragma unroll
    for (int i = 0; i < 4; i++) {
        float4 v = make_float4(acc[i][0], acc[i][1], acc[i][2], acc[i][3]);
        *(float4*)(out + (size_t)(bi + ty * 4 + i) * NN + bj + (tx << 2)) = v;
    }
}

// ---------------- launch ----------------------------------------------------
extern "C" void kernel_launch(void* const* d_in, const int* in_sizes, int n_in,
                              void* d_out, int out_size) {
    const float* x       = (const float*)d_in[0];
    const float* adj     = (const float*)d_in[1];
    const float* W_heads = (const float*)d_in[2];
    const float* a_heads = (const float*)d_in[3];
    const float* W_att   = (const float*)d_in[4];
    const float* a_att   = (const float*)d_in[5];
    const float* W1      = (const float*)d_in[6];
    const float* W2      = (const float*)d_in[7];
    const float* W3      = (const float*)d_in[8];
    const float* eps     = (const float*)d_in[9];
    float* out = (float*)d_out;
    float* out_mu = out + (size_t)NN * NN;
    float* out_lv = out_mu + (size_t)NN * F3C;

    k_build_gemm1<<<768, 256>>>(adj, x, W_heads, a_heads);  // overlap build + GEMM1
    k_gat1<<<NN, 256>>>();
    k_gemm2<<<NN / 16, 256>>>(W_att, a_att);
    k_gat2_fc1<<<NN, 64>>>(W1);
    k_spmm_fc23<<<NN / 8, 256>>>(W2, W3);
    k_spmm_reparam<<<NN / 16, 256>>>(eps, out_mu, out_lv);
    k_zzT<<<dim3(NN / 64, NN / 64), 256>>>(out);
}

// round 5
// speedup vs baseline: 1.2735x; 1.0271x over previous
#include <cuda_runtime.h>
#include <math.h>

#define NN   4096
#define DD   512
#define F1C  64
#define HC   4
#define HF   256   // HC*F1C
#define F2C  32
#define F3C  16
#define MAXD 128

// packed fp32x2 FMA (Blackwell): d = a*b + c on 2 lanes of a 64-bit reg pair
#define FMA_F32X2(d, a, b, c) \
    asm("fma.rn.f32x2 %0, %1, %2, %3;" : "=l"(d) : "l"(a), "l"(b), "l"(c))
#define PACK2(out, lo, hi) \
    asm("mov.b64 %0, {%1, %2};" : "=l"(out) : "r"(lo), "r"(hi))
#define UNPACK2(lo, hi, in) \
    asm("mov.b64 {%0, %1}, %2;" : "=r"(lo), "=r"(hi) : "l"(in))

// ---------------- scratch (device globals; no allocation allowed) ----------
__device__ int   g_deg[NN];
__device__ int   g_cols[NN * MAXD];
__device__ float g_WhAll[NN * HF];     // Wh for 4 heads, [i][h*64+f]
__device__ float g_s1h[HC * NN];
__device__ float g_s2h[HC * NN];
__device__ float g_cat[NN * HF];       // concat of head outputs
__device__ float g_Wh2[NN * F1C];      // cat @ W_att
__device__ float g_s1b[NN];
__device__ float g_s2b[NN];
__device__ float g_t1[NN * F2C];       // gc_att @ W1
__device__ float g_t2[NN * F3C];       // h1 @ W2
__device__ float g_t3[NN * F3C];       // h1 @ W3
__device__ float g_z[NN * F3C];

// ============ fused: blocks [0,256) do GEMM1 tiles, [256,768) build ELL =====
__global__ void k_build_gemm1(const float* __restrict__ adj,
                              const float* __restrict__ x,
                              const float* __restrict__ W_heads,
                              const float* __restrict__ a_heads) {
    __shared__ __align__(16) float sA[16][64];
    __shared__ __align__(16) float sB[16][64];
    int bx = blockIdx.x;
    if (bx >= 256) {
        // ---- adjacency build: warp per row (float4 scan + ballot compact) --
        int wb = bx - 256;
        int row = wb * 8 + (threadIdx.x >> 5);
        int lane = threadIdx.x & 31;
        const float4* arow = (const float4*)(adj + (size_t)row * NN);
        int cnt = 0;
        for (int j0 = 0; j0 < NN; j0 += 128) {
            float4 v = arow[(j0 >> 2) + lane];
            int base = j0 + lane * 4;
#pragma unroll
            for (int c = 0; c < 4; c++) {
                float val = (c == 0) ? v.x : (c == 1) ? v.y : (c == 2) ? v.z : v.w;
                unsigned m = __ballot_sync(0xffffffffu, val > 0.f);
                if (val > 0.f) {
                    int pos = cnt + __popc(m & ((1u << lane) - 1u));
                    if (pos < MAXD) g_cols[row * MAXD + pos] = base + c;
                }
                cnt += __popc(m);
            }
        }
        if (lane == 0) g_deg[row] = cnt < MAXD ? cnt : MAXD;
        return;
    }
    // ---- GEMM1 tile: head = bx>>6, row-block = bx&63 -----------------------
    int head = bx >> 6;
    int bm = (bx & 63) << 6;
    int tid = threadIdx.x;
    int ty = tid >> 4, tx = tid & 15;
    const float* B = W_heads + (size_t)head * DD * F1C;
    unsigned long long acc2[4][2] = {};
    for (int k0 = 0; k0 < DD; k0 += 16) {
        int ar = tid >> 2, kq = (tid & 3) << 2;
        float4 va = *(const float4*)(x + (size_t)(bm + ar) * DD + k0 + kq);
        sA[kq + 0][ar] = va.x; sA[kq + 1][ar] = va.y;
        sA[kq + 2][ar] = va.z; sA[kq + 3][ar] = va.w;
        int br = tid >> 4, nq = (tid & 15) << 2;
        *(float4*)&sB[br][nq] = *(const float4*)(B + (size_t)(k0 + br) * F1C + nq);
        __syncthreads();
#pragma unroll
        for (int kk = 0; kk < 16; kk++) {
            float4 av = *(const float4*)&sA[kk][ty << 2];
            ulonglong2 bb = *(const ulonglong2*)&sB[kk][tx << 2];
            unsigned long long ap;
            PACK2(ap, __float_as_uint(av.x), __float_as_uint(av.x));
            FMA_F32X2(acc2[0][0], ap, bb.x, acc2[0][0]);
            FMA_F32X2(acc2[0][1], ap, bb.y, acc2[0][1]);
            PACK2(ap, __float_as_uint(av.y), __float_as_uint(av.y));
            FMA_F32X2(acc2[1][0], ap, bb.x, acc2[1][0]);
            FMA_F32X2(acc2[1][1], ap, bb.y, acc2[1][1]);
            PACK2(ap, __float_as_uint(av.z), __float_as_uint(av.z));
            FMA_F32X2(acc2[2][0], ap, bb.x, acc2[2][0]);
            FMA_F32X2(acc2[2][1], ap, bb.y, acc2[2][1]);
            PACK2(ap, __float_as_uint(av.w), __float_as_uint(av.w));
            FMA_F32X2(acc2[3][0], ap, bb.x, acc2[3][0]);
            FMA_F32X2(acc2[3][1], ap, bb.y, acc2[3][1]);
        }
        __syncthreads();
    }
    float acc[4][4];
#pragma unroll
    for (int i = 0; i < 4; i++) {
        unsigned u0, u1, u2, u3;
        UNPACK2(u0, u1, acc2[i][0]);
        UNPACK2(u2, u3, acc2[i][1]);
        acc[i][0] = __uint_as_float(u0); acc[i][1] = __uint_as_float(u1);
        acc[i][2] = __uint_as_float(u2); acc[i][3] = __uint_as_float(u3);
    }
#pragma unroll
    for (int i = 0; i < 4; i++) {
        float4 v = make_float4(acc[i][0], acc[i][1], acc[i][2], acc[i][3]);
        *(float4*)(g_WhAll + (size_t)(bm + ty * 4 + i) * HF + head * F1C + (tx << 2)) = v;
    }
    // score epilogue
    const float* ag = a_heads + head * 2 * F1C;
    float a1v[4], a2v[4];
#pragma unroll
    for (int c = 0; c < 4; c++) { a1v[c] = ag[(tx << 2) + c]; a2v[c] = ag[F1C + (tx << 2) + c]; }
#pragma unroll
    for (int i = 0; i < 4; i++) {
        float p1 = acc[i][0] * a1v[0] + acc[i][1] * a1v[1] + acc[i][2] * a1v[2] + acc[i][3] * a1v[3];
        float p2 = acc[i][0] * a2v[0] + acc[i][1] * a2v[1] + acc[i][2] * a2v[2] + acc[i][3] * a2v[3];
#pragma unroll
        for (int o = 8; o; o >>= 1) {
            p1 += __shfl_xor_sync(0xffffffffu, p1, o);
            p2 += __shfl_xor_sync(0xffffffffu, p2, o);
        }
        if (tx == 0) {
            int row = bm + ty * 4 + i;
            g_s1h[head * NN + row] = p1;
            g_s2h[head * NN + row] = p2;
        }
    }
}

// ---------------- GAT1: warp-per-head softmax + block aggregation + ELU ----
__global__ void k_gat1() {
    __shared__ int   sc[MAXD];
    __shared__ float sw[HC * MAXD];
    __shared__ float sinv[HC];
    int row = blockIdx.x;
    int tid = threadIdx.x;
    int deg = g_deg[row];
    for (int j = tid; j < deg; j += 256) sc[j] = g_cols[row * MAXD + j];
    __syncthreads();
    int wid = tid >> 5, lane = tid & 31;
    if (wid < HC) {
        int g = wid;
        float s1i = g_s1h[g * NN + row];
        float m = -1e30f;
        for (int j = lane; j < deg; j += 32) {
            float e = s1i + g_s2h[g * NN + sc[j]];
            e = e >= 0.f ? e : 0.2f * e;             // leaky_relu(0.2)
            sw[g * MAXD + j] = e;
            m = fmaxf(m, e);
        }
#pragma unroll
        for (int o = 16; o; o >>= 1) m = fmaxf(m, __shfl_xor_sync(0xffffffffu, m, o));
        float s = 0.f;
        for (int j = lane; j < deg; j += 32) {
            float w = expf(sw[g * MAXD + j] - m);
            sw[g * MAXD + j] = w;
            s += w;
        }
#pragma unroll
        for (int o = 16; o; o >>= 1) s += __shfl_xor_sync(0xffffffffu, s, o);
        if (lane == 0) sinv[g] = 1.f / s;
    }
    __syncthreads();
    int g = tid >> 6, f = tid & 63;
    const float* base = g_WhAll + g * F1C + f;
    const float* wp = sw + g * MAXD;
    float ac0 = 0.f, ac1 = 0.f, ac2 = 0.f, ac3 = 0.f;
    int j = 0;
    for (; j + 4 <= deg; j += 4) {
        ac0 += wp[j + 0] * base[(size_t)sc[j + 0] * HF];
        ac1 += wp[j + 1] * base[(size_t)sc[j + 1] * HF];
        ac2 += wp[j + 2] * base[(size_t)sc[j + 2] * HF];
        ac3 += wp[j + 3] * base[(size_t)sc[j + 3] * HF];
    }
    for (; j < deg; j++) ac0 += wp[j] * base[(size_t)sc[j] * HF];
    float acc = ((ac0 + ac1) + (ac2 + ac3)) * sinv[g];
    g_cat[(size_t)row * HF + g * F1C + f] = acc > 0.f ? acc : expm1f(acc);   // ELU
}

// ---------------- GEMM2: Wh2 = cat @ W_att, BM=16 (256 CTAs) + scores ------
__global__ void k_gemm2(const float* __restrict__ W_att,
                        const float* __restrict__ a_att) {
    __shared__ __align__(16) float sA[32][17];   // transposed [k][row]
    __shared__ __align__(16) float sB[32][64];
    int bm = blockIdx.x << 4;
    int tid = threadIdx.x;
    int row = tid >> 4, cq = (tid & 15) << 2;
    unsigned long long acc2[2] = {};
    for (int k0 = 0; k0 < HF; k0 += 32) {
        if (tid < 128) {
            int r = tid >> 3, kq = (tid & 7) << 2;
            float4 va = *(const float4*)(g_cat + (size_t)(bm + r) * HF + k0 + kq);
            sA[kq + 0][r] = va.x; sA[kq + 1][r] = va.y;
            sA[kq + 2][r] = va.z; sA[kq + 3][r] = va.w;
        }
#pragma unroll
        for (int t = 0; t < 2; t++) {
            int idx = tid + t * 256;
            int kr = idx >> 4, bq = (idx & 15) << 2;
            *(float4*)&sB[kr][bq] = *(const float4*)(W_att + (size_t)(k0 + kr) * F1C + bq);
        }
        __syncthreads();
#pragma unroll
        for (int kk = 0; kk < 32; kk++) {
            float a = sA[kk][row];
            ulonglong2 bb = *(const ulonglong2*)&sB[kk][cq];
            unsigned long long ap;
            PACK2(ap, __float_as_uint(a), __float_as_uint(a));
            FMA_F32X2(acc2[0], ap, bb.x, acc2[0]);
            FMA_F32X2(acc2[1], ap, bb.y, acc2[1]);
        }
        __syncthreads();
    }
    unsigned u0, u1, u2, u3;
    UNPACK2(u0, u1, acc2[0]);
    UNPACK2(u2, u3, acc2[1]);
    float acc0 = __uint_as_float(u0), acc1 = __uint_as_float(u1);
    float acc3v = __uint_as_float(u3), acc2v = __uint_as_float(u2);
    float4 v = make_float4(acc0, acc1, acc2v, acc3v);
    *(float4*)(g_Wh2 + (size_t)(bm + row) * F1C + cq) = v;
    float p1 = acc0 * a_att[cq] + acc1 * a_att[cq + 1] + acc2v * a_att[cq + 2] + acc3v * a_att[cq + 3];
    float p2 = acc0 * a_att[F1C + cq] + acc1 * a_att[F1C + cq + 1]
             + acc2v * a_att[F1C + cq + 2] + acc3v * a_att[F1C + cq + 3];
#pragma unroll
    for (int o = 8; o; o >>= 1) {
        p1 += __shfl_xor_sync(0xffffffffu, p1, o);
        p2 += __shfl_xor_sync(0xffffffffu, p2, o);
    }
    if ((tid & 15) == 0) {
        g_s1b[bm + row] = p1;
        g_s2b[bm + row] = p2;
    }
}

// ---------------- GAT2 + fc1: 4 rows per block (256 thr), warp softmax -----
__global__ void k_gat2_fc1(const float* __restrict__ W1) {
    __shared__ int   sc[4][MAXD];
    __shared__ float sw[4][MAXD];
    __shared__ float sinv[4];
    __shared__ float sgc[4][F1C];
    int tid = threadIdx.x;
    int grp = tid >> 6, gt = tid & 63;        // 4 groups of 64 threads
    int row = blockIdx.x * 4 + grp;
    int deg = g_deg[row];
    for (int j = gt; j < deg; j += 64) sc[grp][j] = g_cols[row * MAXD + j];
    __syncthreads();
    if (gt < 32) {                             // warp 2*grp does softmax
        int lane = gt;
        float s1i = g_s1b[row];
        float m = -1e30f;
        for (int j = lane; j < deg; j += 32) {
            float e = s1i + g_s2b[sc[grp][j]];
            e = e >= 0.f ? e : 0.2f * e;
            sw[grp][j] = e;
            m = fmaxf(m, e);
        }
#pragma unroll
        for (int o = 16; o; o >>= 1) m = fmaxf(m, __shfl_xor_sync(0xffffffffu, m, o));
        float s = 0.f;
        for (int j = lane; j < deg; j += 32) {
            float w = expf(sw[grp][j] - m);
            sw[grp][j] = w;
            s += w;
        }
#pragma unroll
        for (int o = 16; o; o >>= 1) s += __shfl_xor_sync(0xffffffffu, s, o);
        if (lane == 0) sinv[grp] = 1.f / s;
    }
    __syncthreads();
    const float* base = g_Wh2 + gt;
    const int* cp = sc[grp];
    const float* wp = sw[grp];
    float ac0 = 0.f, ac1 = 0.f, ac2 = 0.f, ac3 = 0.f;
    int j = 0;
    for (; j + 4 <= deg; j += 4) {
        ac0 += wp[j + 0] * base[(size_t)cp[j + 0] * F1C];
        ac1 += wp[j + 1] * base[(size_t)cp[j + 1] * F1C];
        ac2 += wp[j + 2] * base[(size_t)cp[j + 2] * F1C];
        ac3 += wp[j + 3] * base[(size_t)cp[j + 3] * F1C];
    }
    for (; j < deg; j++) ac0 += wp[j] * base[(size_t)cp[j] * F1C];
    float acc = ((ac0 + ac1) + (ac2 + ac3)) * sinv[grp];
    sgc[grp][gt] = acc > 0.f ? acc : expm1f(acc);   // ELU
    __syncthreads();
    if (gt < F2C) {
        float t = 0.f;
#pragma unroll 16
        for (int k = 0; k < F1C; k++) t += sgc[grp][k] * W1[k * F2C + gt];
        g_t1[row * F2C + gt] = t;
    }
}

// ---------------- h1 = relu(adj@t1) fused with t2=h1@W2, t3=h1@W3 ----------
__global__ void k_spmm_fc23(const float* __restrict__ W2,
                            const float* __restrict__ W3) {
    __shared__ float sh[8][F2C];
    __shared__ float w2[F2C * F3C], w3[F2C * F3C];
    int tid = threadIdx.x;                            // 256 threads
    for (int k = tid; k < F2C * F3C; k += 256) { w2[k] = W2[k]; w3[k] = W3[k]; }
    int wid = tid >> 5, lane = tid & 31;
    int row = blockIdx.x * 8 + wid;
    int deg = g_deg[row];
    const int* cp = g_cols + row * MAXD;
    float a0 = 0.f, a1 = 0.f, a2 = 0.f, a3 = 0.f;
    int j = 0;
    for (; j + 4 <= deg; j += 4) {
        a0 += g_t1[cp[j + 0] * F2C + lane];
        a1 += g_t1[cp[j + 1] * F2C + lane];
        a2 += g_t1[cp[j + 2] * F2C + lane];
        a3 += g_t1[cp[j + 3] * F2C + lane];
    }
    for (; j < deg; j++) a0 += g_t1[cp[j] * F2C + lane];
    sh[wid][lane] = fmaxf((a0 + a1) + (a2 + a3), 0.f);
    __syncthreads();
    int r = tid >> 5, o = tid & 31, f = o & 15;
    const float* w = (o < 16) ? w2 : w3;
    float v = 0.f;
#pragma unroll 8
    for (int k = 0; k < F2C; k++) v += sh[r][k] * w[k * F3C + f];
    float* dst = (o < 16) ? g_t2 : g_t3;
    dst[(blockIdx.x * 8 + r) * F3C + f] = v;
}

// ---------------- mu/logvar spmm + reparameterize --------------------------
__global__ void k_spmm_reparam(const float* __restrict__ eps,
                               float* __restrict__ out_mu,
                               float* __restrict__ out_lv) {
    int tid = threadIdx.x;
    int row = blockIdx.x * 16 + (tid >> 4);
    int f = tid & 15;
    int deg = g_deg[row];
    const int* cp = g_cols + row * MAXD;
    float m0 = 0.f, m1 = 0.f, l0 = 0.f, l1 = 0.f;
    int j = 0;
    for (; j + 2 <= deg; j += 2) {
        int c0 = cp[j], c1 = cp[j + 1];
        m0 += g_t2[c0 * F3C + f];
        l0 += g_t3[c0 * F3C + f];
        m1 += g_t2[c1 * F3C + f];
        l1 += g_t3[c1 * F3C + f];
    }
    if (j < deg) { int c = cp[j]; m0 += g_t2[c * F3C + f]; l0 += g_t3[c * F3C + f]; }
    float mu = m0 + m1, lv = l0 + l1;
    int o = row * F3C + f;
    out_mu[o] = mu;
    out_lv[o] = lv;
    g_z[o] = eps[o] * expf(lv) + mu;
}

// ---------------- adj_rec = z @ z^T (64x64 tile, K=16, write-bound) --------
__global__ void k_zzT(float* __restrict__ out) {
    __shared__ float sa[64][17];
    __shared__ float sb[64][17];
    int bi = blockIdx.y << 6, bj = blockIdx.x << 6;
    int tid = threadIdx.x;
    int r = tid >> 2, q = (tid & 3) << 2;
    float4 va = *(const float4*)(g_z + ((bi + r) << 4) + q);
    sa[r][q + 0] = va.x; sa[r][q + 1] = va.y; sa[r][q + 2] = va.z; sa[r][q + 3] = va.w;
    float4 vb = *(const float4*)(g_z + ((bj + r) << 4) + q);
    sb[r][q + 0] = vb.x; sb[r][q + 1] = vb.y; sb[r][q + 2] = vb.z; sb[r][q + 3] = vb.w;
    __syncthreads();
    int ty = tid >> 4, tx = tid & 15;
    float acc[4][4] = {};
#pragma unroll
    for (int k = 0; k < 16; k++) {
        float a0 = sa[ty * 4 + 0][k], a1 = sa[ty * 4 + 1][k];
        float a2 = sa[ty * 4 + 2][k], a3 = sa[ty * 4 + 3][k];
        float b0 = sb[tx * 4 + 0][k], b1 = sb[tx * 4 + 1][k];
        float b2 = sb[tx * 4 + 2][k], b3 = sb[tx * 4 + 3][k];
        acc[0][0] += a0 * b0; acc[0][1] += a0 * b1; acc[0][2] += a0 * b2; acc[0][3] += a0 * b3;
        acc[1][0] += a1 * b0; acc[1][1] += a1 * b1; acc[1][2] += a1 * b2; acc[1][3] += a1 * b3;
        acc[2][0] += a2 * b0; acc[2][1] += a2 * b1; acc[2][2] += a2 * b2; acc[2][3] += a2 * b3;
        acc[3][0] += a3 * b0; acc[3][1] += a3 * b1; acc[3][2] += a3 * b2; acc[3][3] += a3 * b3;
    }
#pragma unroll
    for (int i = 0; i < 4; i++) {
        float4 v = make_float4(acc[i][0], acc[i][1], acc[i][2], acc[i][3]);
        *(float4*)(out + (size_t)(bi + ty * 4 + i) * NN + bj + (tx << 2)) = v;
    }
}

// ---------------- launch ----------------------------------------------------
extern "C" void kernel_launch(void* const* d_in, const int* in_sizes, int n_in,
                              void* d_out, int out_size) {
    const float* x       = (const float*)d_in[0];
    const float* adj     = (const float*)d_in[1];
    const float* W_heads = (const float*)d_in[2];
    const float* a_heads = (const float*)d_in[3];
    const float* W_att   = (const float*)d_in[4];
    const float* a_att   = (const float*)d_in[5];
    const float* W1      = (const float*)d_in[6];
    const float* W2      = (const float*)d_in[7];
    const float* W3      = (const float*)d_in[8];
    const float* eps     = (const float*)d_in[9];
    float* out = (float*)d_out;
    float* out_mu = out + (size_t)NN * NN;
    float* out_lv = out_mu + (size_t)NN * F3C;

    k_build_gemm1<<<768, 256>>>(adj, x, W_heads, a_heads);  // overlap build + GEMM1
    k_gat1<<<NN, 256>>>();
    k_gemm2<<<NN / 16, 256>>>(W_att, a_att);
    k_gat2_fc1<<<NN / 4, 256>>>(W1);
    k_spmm_fc23<<<NN / 8, 256>>>(W2, W3);
    k_spmm_reparam<<<NN / 16, 256>>>(eps, out_mu, out_lv);
    k_zzT<<<dim3(NN / 64, NN / 64), 256>>>(out);
}